// round 13
// baseline (speedup 1.0000x reference)
#include <cuda_runtime.h>
#include <cstdint>

#define NN 8192
#define IN_F 256
#define OUT_F 64
#define LEAK 0.2f

// ---------------- scratch (device globals; no runtime allocation) ----------
__device__ float  g_h[NN * OUT_F];     // tf32-rounded h, row-major [j][f]
__device__ float4 g_rowEFG[NN];        // (exp(si), exp(.2 si), -, -)
__device__ float2 g_ef[NN];            // (exp(sj), exp(.2 sj))
__device__ float  g_gamma[NN];
__device__ float  g_beta[NN];

// ---------------- helpers ---------------------------------------------------
__device__ __forceinline__ float to_tf32(float x) {
    uint32_t u;
    asm("cvt.rna.tf32.f32 %0, %1;" : "=r"(u) : "f"(x));
    return __uint_as_float(u);
}

__device__ __forceinline__ uint32_t smem_u32(const void* p) {
    uint32_t a;
    asm("{ .reg .u64 t; cvta.to.shared.u64 t, %1; cvt.u32.u64 %0, t; }"
        : "=r"(a) : "l"(p));
    return a;
}

__device__ __forceinline__ void mma_tf32(float& c0, float& c1, float& c2, float& c3,
                                         uint32_t a0, uint32_t a1, uint32_t a2, uint32_t a3,
                                         uint32_t b0, uint32_t b1)
{
    asm volatile("mma.sync.aligned.m16n8k8.row.col.f32.tf32.tf32.f32 "
                 "{%0,%1,%2,%3}, {%4,%5,%6,%7}, {%8,%9}, {%0,%1,%2,%3};"
                 : "+f"(c0), "+f"(c1), "+f"(c2), "+f"(c3)
                 : "r"(a0), "r"(a1), "r"(a2), "r"(a3), "r"(b0), "r"(b1));
}

#define CP_ASYNC16(dst, src) \
    asm volatile("cp.async.cg.shared.global [%0], [%1], 16;" :: "r"(dst), "l"(src) : "memory")
#define CP_COMMIT() asm volatile("cp.async.commit_group;" ::: "memory")
#define CP_WAIT0()  asm volatile("cp.async.wait_group 0;" ::: "memory")

// ============================================================================
// Kernel 1: h = x @ W ; E/F factors, gamma, beta ; g_h tf32-rounded
// 256 blocks x 512 threads, 32 rows/block (2 blocks/SM).  (unchanged)
// ============================================================================
#define XSTR 260
#define PREP_SMEM ((IN_F * OUT_F + 32 * XSTR + 4 * OUT_F) * 4)

__global__ __launch_bounds__(512, 2) void prep_kernel(
    const float* __restrict__ x, const float* __restrict__ W,
    const float* __restrict__ a_i, const float* __restrict__ a_j,
    const float* __restrict__ w_g, const float* __restrict__ w_b)
{
    extern __shared__ float sm[];
    float* Ws = sm;                          // [256][64] (float4-read)
    float* xs = Ws + IN_F * OUT_F;           // [32][XSTR]
    float* vs = xs + 32 * XSTR;              // 4 x [64]

    const int t = threadIdx.x;
    const int row0 = blockIdx.x * 32;

    for (int i = t; i < IN_F * OUT_F / 4; i += 512)
        ((float4*)Ws)[i] = ((const float4*)W)[i];
    for (int c = t; c < 32 * 64; c += 512) {
        const int row = c >> 6, k4 = c & 63;
        *(float4*)&xs[row * XSTR + k4 * 4] =
            ((const float4*)(x + (size_t)(row0 + row) * IN_F))[k4];
    }
    if (t < OUT_F) {
        vs[t]             = a_i[t];
        vs[OUT_F + t]     = a_j[t];
        vs[2 * OUT_F + t] = w_g[t];
        vs[3 * OUT_F + t] = w_b[t];
    }
    __syncthreads();

    const int row = t >> 4;        // 0..31
    const int fg  = t & 15;        // 0..15
    const int f0  = fg * 4;

    float4 acc = make_float4(0.f, 0.f, 0.f, 0.f);
    const float*  xr  = xs + row * XSTR;
    const float4* Ws4 = (const float4*)Ws;
#pragma unroll 8
    for (int k = 0; k < IN_F; k++) {
        const float xv = xr[k];
        const float4 w4 = Ws4[k * 16 + fg];
        acc.x = fmaf(xv, w4.x, acc.x);
        acc.y = fmaf(xv, w4.y, acc.y);
        acc.z = fmaf(xv, w4.z, acc.z);
        acc.w = fmaf(xv, w4.w, acc.w);
    }

    const int grow = row0 + row;
    *(float4*)(g_h + (size_t)grow * OUT_F + f0) =
        make_float4(to_tf32(acc.x), to_tf32(acc.y), to_tf32(acc.z), to_tf32(acc.w));

    float psi = acc.x * vs[f0]     + acc.y * vs[f0 + 1]     + acc.z * vs[f0 + 2]     + acc.w * vs[f0 + 3];
    float psj = acc.x * vs[64+f0]  + acc.y * vs[64+f0 + 1]  + acc.z * vs[64+f0 + 2]  + acc.w * vs[64+f0 + 3];
    float pg  = acc.x * vs[128+f0] + acc.y * vs[128+f0 + 1] + acc.z * vs[128+f0 + 2] + acc.w * vs[128+f0 + 3];
    float pb  = acc.x * vs[192+f0] + acc.y * vs[192+f0 + 1] + acc.z * vs[192+f0 + 2] + acc.w * vs[192+f0 + 3];
#pragma unroll
    for (int off = 8; off > 0; off >>= 1) {
        psi += __shfl_down_sync(0xffffffffu, psi, off, 16);
        psj += __shfl_down_sync(0xffffffffu, psj, off, 16);
        pg  += __shfl_down_sync(0xffffffffu, pg,  off, 16);
        pb  += __shfl_down_sync(0xffffffffu, pb,  off, 16);
    }
    if (fg == 0) {
        g_rowEFG[grow] = make_float4(__expf(psi), __expf(LEAK * psi), 0.f, 0.f);
        g_ef[grow]     = make_float2(__expf(psj), __expf(LEAK * psj));
        g_gamma[grow]  = pg + 1.0f;
        g_beta[grow]   = pb;
    }
}

// ============================================================================
// Kernel 2: fused masked softmax-attention via mma.sync tf32 + FiLM.
// 256 blocks x 512 threads (16 warps), TWO blocks per SM — one block's
// compute fills the other's barrier/drain bubbles. Block = 32 rows, BN=128.
// Warp grid: kh = wid&7 (K-eighth) x mh = wid>>3 (M-half, 16 rows); 32 accums.
// 2-stage cp.async pipeline (adj + h + EF), fused per-warp gen+mma.
// ============================================================================
#define BN   128
#define ASTR 132
#define HSTR 72
#define PSTR 68

#define OFF_H    0                       // 2 x 128 x 72 = 18432 floats
#define OFF_ADJ  18432                   // 2 x 32 x 132 = 8448 (ints)
#define OFF_EF   26880                   // 2 x 256 = 512
#define OFF_DENP 27392                   // 8 x 32 = 256
#define SMEM_FLOATS 27648
#define ATTN_SMEM (SMEM_FLOATS * 4)      // 110592 B -> 2 blocks = 216KB/SM
// epilogue partials [8][32][68] = 17408 floats overlay at offset 0

__global__ __launch_bounds__(512, 2) void attn_kernel(
    const int* __restrict__ adj, float* __restrict__ out)
{
    extern __shared__ float sf[];
    const uint32_t sbase = smem_u32(sf);

    const int t    = threadIdx.x;
    const int lane = t & 31;
    const int wid  = t >> 5;
    const int g    = lane >> 2;   // mma groupID
    const int tg   = lane & 3;    // mma threadID-in-group
    const int i0   = blockIdx.x * 32;

    const int r  = t >> 4;        // staging row 0..31
    const int cc = t & 15;        // staging chunk lane 0..15

    const int kh = wid & 7;       // K-eighth
    const int mh = wid >> 3;      // M-half (16 rows)

    const int m0 = mh * 16 + g;   // this thread's two w rows (0..31)
    const int m1 = m0 + 8;
    const float4 efg0 = g_rowEFG[i0 + m0];
    const float4 efg1 = g_rowEFG[i0 + m1];
    const float Ei0 = efg0.x, Fi0 = efg0.y;
    const float Ei1 = efg1.x, Fi1 = efg1.y;

    const char* adj_row = (const char*)(adj + (size_t)(i0 + r) * NN);

    // hoisted staging addresses (bytes)
    const uint32_t adj_dst0 = sbase + (OFF_ADJ + r * ASTR + cc * 4) * 4;
    const uint32_t ef_dst   = sbase + (OFF_EF + t * 4) * 4;   // t<64 only
    const uint32_t ADJ_BUFB = 32 * ASTR * 4;
    const uint32_t H_BUFB   = 128 * HSTR * 4;
    const uint32_t EF_BUFB  = 256 * 4;
    // h chunks: c = t + i*512, i = 0..3 (2048 chunks of 16B)
    uint32_t h_dst[4];
#pragma unroll
    for (int i = 0; i < 4; i++) {
        const int hc = t + i * 512;
        h_dst[i] = sbase + (OFF_H + (hc >> 4) * HSTR + (hc & 15) * 4) * 4;
    }

    // ---- prologue: tile 0 (adj, h, EF) via cp.async ----
    {
        CP_ASYNC16(adj_dst0,           adj_row + cc * 16);
        CP_ASYNC16(adj_dst0 + 16 * 16, adj_row + (cc + 16) * 16);
#pragma unroll
        for (int i = 0; i < 4; i++)
            CP_ASYNC16(h_dst[i], (const char*)g_h + (t + i * 512) * 16);
        if (t < 64) CP_ASYNC16(ef_dst, (const char*)g_ef + t * 16);
        CP_COMMIT();
    }

    float acc[8][4];
#pragma unroll
    for (int b = 0; b < 8; b++)
#pragma unroll
        for (int c = 0; c < 4; c++) acc[b][c] = 0.0f;
    float dsum0 = 0.0f, dsum1 = 0.0f;

    for (int tile = 0; tile < NN / BN; tile++) {
        const int buf = tile & 1;
        CP_WAIT0();
        __syncthreads();   // tile data ready; prev tile's reads complete

        // ---- prefetch next tile ----
        if (tile + 1 < NN / BN) {
            const uint32_t nb = (buf ^ 1);
            const int j1 = (tile + 1) * BN;
            const char* asrc = adj_row + (size_t)j1 * 4;
            CP_ASYNC16(adj_dst0 + nb * ADJ_BUFB,           asrc + cc * 16);
            CP_ASYNC16(adj_dst0 + nb * ADJ_BUFB + 16 * 16, asrc + (cc + 16) * 16);
            const char* hsrc = (const char*)(g_h + (size_t)j1 * OUT_F);
#pragma unroll
            for (int i = 0; i < 4; i++)
                CP_ASYNC16(h_dst[i] + nb * H_BUFB, hsrc + (t + i * 512) * 16);
            if (t < 64) CP_ASYNC16(ef_dst + nb * EF_BUFB,
                                   (const char*)(g_ef + j1) + t * 16);
            CP_COMMIT();
        }

        // ---- fused gen + mma (per-warp; no further barriers this tile) ----
        const int*      adjS = (const int*)(sf + OFF_ADJ) + buf * (32 * ASTR);
        const float2*   efS  = (const float2*)(sf + OFF_EF) + buf * 128;
        const uint32_t* hsu  = (const uint32_t*)(sf + OFF_H) + buf * (128 * HSTR);

#pragma unroll
        for (int kc = 0; kc < 2; kc++) {
            const int k0 = kh * 16 + kc * 8;
            const int kA = k0 + tg;
            const int kB = kA + 4;
            const float2 efA = efS[kA];
            const float2 efB = efS[kB];
            const int a00 = adjS[m0 * ASTR + kA];
            const int a10 = adjS[m1 * ASTR + kA];
            const int a01 = adjS[m0 * ASTR + kB];
            const int a11 = adjS[m1 * ASTR + kB];

            float w00, w10, w01, w11;
            { const float p = Ei0 * efA.x; const float q = Fi0 * efA.y;
              w00 = (p > 1.0f) ? p : q; w00 = a00 ? w00 : 0.0f; }
            { const float p = Ei1 * efA.x; const float q = Fi1 * efA.y;
              w10 = (p > 1.0f) ? p : q; w10 = a10 ? w10 : 0.0f; }
            { const float p = Ei0 * efB.x; const float q = Fi0 * efB.y;
              w01 = (p > 1.0f) ? p : q; w01 = a01 ? w01 : 0.0f; }
            { const float p = Ei1 * efB.x; const float q = Fi1 * efB.y;
              w11 = (p > 1.0f) ? p : q; w11 = a11 ? w11 : 0.0f; }

            dsum0 += w00 + w01;
            dsum1 += w10 + w11;

            const uint32_t ka0 = __float_as_uint(to_tf32(w00));
            const uint32_t ka1 = __float_as_uint(to_tf32(w10));
            const uint32_t ka2 = __float_as_uint(to_tf32(w01));
            const uint32_t ka3 = __float_as_uint(to_tf32(w11));

#pragma unroll
            for (int nt = 0; nt < 8; nt++) {
                const uint32_t b0 = hsu[kA * HSTR + nt * 8 + g];
                const uint32_t b1 = hsu[kB * HSTR + nt * 8 + g];
                float* c = acc[nt];
                mma_tf32(c[0], c[1], c[2], c[3], ka0, ka1, ka2, ka3, b0, b1);
            }
        }
    }

    __syncthreads();   // all warps done with smem tiles

    // ---- denominators: reduce over tg lanes (groups of 4), stage per kh ----
    dsum0 += __shfl_down_sync(0xffffffffu, dsum0, 2, 4);
    dsum0 += __shfl_down_sync(0xffffffffu, dsum0, 1, 4);
    dsum1 += __shfl_down_sync(0xffffffffu, dsum1, 2, 4);
    dsum1 += __shfl_down_sync(0xffffffffu, dsum1, 1, 4);
    if (tg == 0) {
        sf[OFF_DENP + kh * 32 + m0] = dsum0;
        sf[OFF_DENP + kh * 32 + m1] = dsum1;
    }

    // ---- stage K-split output partials (overlay on tile smem) ----
    {
        float* part = sf + kh * (32 * PSTR);
#pragma unroll
        for (int nt = 0; nt < 8; nt++) {
            const float* c = acc[nt];
            const int n = nt * 8 + tg * 2;
            *(float2*)&part[m0 * PSTR + n] = make_float2(c[0], c[1]);
            *(float2*)&part[m1 * PSTR + n] = make_float2(c[2], c[3]);
        }
    }
    __syncthreads();

    // ---- reduce 8 partials + FiLM + store (4 outputs/thread) ----
    {
        const int m  = t >> 4;        // 0..31
        const int n0 = (t & 15) * 4;
        float den = 0.f;
#pragma unroll
        for (int w = 0; w < 8; w++) den += sf[OFF_DENP + w * 32 + m];
        const float inv = 1.0f / den;
        const float gm  = g_gamma[i0 + m];
        const float bt  = g_beta[i0 + m];
        float sx = 0.f, sy = 0.f, sz = 0.f, sw = 0.f;
#pragma unroll
        for (int w = 0; w < 8; w++) {
            const float4 p = *(const float4*)&sf[w * (32 * PSTR) + m * PSTR + n0];
            sx += p.x; sy += p.y; sz += p.z; sw += p.w;
        }
        *(float4*)(out + (size_t)(i0 + m) * OUT_F + n0) =
            make_float4(fmaf(gm, sx * inv, bt), fmaf(gm, sy * inv, bt),
                        fmaf(gm, sz * inv, bt), fmaf(gm, sw * inv, bt));
    }
}

// ============================================================================
extern "C" void kernel_launch(void* const* d_in, const int* in_sizes, int n_in,
                              void* d_out, int out_size)
{
    const float* x   = (const float*)d_in[0];
    const int*   adj = (const int*)d_in[1];
    const float* W   = (const float*)d_in[2];
    const float* a_i = (const float*)d_in[3];
    const float* a_j = (const float*)d_in[4];
    const float* w_g = (const float*)d_in[5];
    const float* w_b = (const float*)d_in[6];
    float* out = (float*)d_out;

    cudaFuncSetAttribute(prep_kernel, cudaFuncAttributeMaxDynamicSharedMemorySize, PREP_SMEM);
    cudaFuncSetAttribute(attn_kernel, cudaFuncAttributeMaxDynamicSharedMemorySize, ATTN_SMEM);

    prep_kernel<<<NN / 32, 512, PREP_SMEM>>>(x, W, a_i, a_j, w_g, w_b);
    attn_kernel<<<NN / 32, 512, ATTN_SMEM>>>(adj, out);
}

// round 14
// speedup vs baseline: 1.1538x; 1.1538x over previous
#include <cuda_runtime.h>
#include <cstdint>

#define NN 8192
#define IN_F 256
#define OUT_F 64
#define LEAK 0.2f

// ---------------- scratch (device globals; no runtime allocation) ----------
__device__ float  g_h[NN * OUT_F];     // tf32-rounded h, row-major [j][f]
__device__ float4 g_rowEFG[NN];        // (exp(si), exp(.2 si), -, -)
__device__ float2 g_ef[NN];            // (exp(sj), exp(.2 sj))
__device__ float  g_gamma[NN];
__device__ float  g_beta[NN];

// ---------------- helpers ---------------------------------------------------
__device__ __forceinline__ float to_tf32(float x) {
    uint32_t u;
    asm("cvt.rna.tf32.f32 %0, %1;" : "=r"(u) : "f"(x));
    return __uint_as_float(u);
}

__device__ __forceinline__ uint32_t smem_u32(const void* p) {
    uint32_t a;
    asm("{ .reg .u64 t; cvta.to.shared.u64 t, %1; cvt.u32.u64 %0, t; }"
        : "=r"(a) : "l"(p));
    return a;
}

__device__ __forceinline__ void mma_tf32(float& c0, float& c1, float& c2, float& c3,
                                         uint32_t a0, uint32_t a1, uint32_t a2, uint32_t a3,
                                         uint32_t b0, uint32_t b1)
{
    asm volatile("mma.sync.aligned.m16n8k8.row.col.f32.tf32.tf32.f32 "
                 "{%0,%1,%2,%3}, {%4,%5,%6,%7}, {%8,%9}, {%0,%1,%2,%3};"
                 : "+f"(c0), "+f"(c1), "+f"(c2), "+f"(c3)
                 : "r"(a0), "r"(a1), "r"(a2), "r"(a3), "r"(b0), "r"(b1));
}

#define CP_ASYNC16(dst, src) \
    asm volatile("cp.async.cg.shared.global [%0], [%1], 16;" :: "r"(dst), "l"(src) : "memory")
#define CP_COMMIT()  asm volatile("cp.async.commit_group;" ::: "memory")
#define CP_WAIT0()   asm volatile("cp.async.wait_group 0;" ::: "memory")
#define CP_WAIT1()   asm volatile("cp.async.wait_group 1;" ::: "memory")

// ============================================================================
// Kernel 1 (REWORKED): h = x @ W ; E/F factors, gamma, beta.
// 128 blocks x 512 threads, 64 rows/block. Thread = 2 rows x 4 features:
// each (2 W-wf + 1 x-wf) per warp per k now feeds 4 rows -> half the
// crossbar traffic of the old layout. x and W staged via cp.async.
// Per-(row,feature) accumulation order identical to previous rounds.
// ============================================================================
#define PXSTR 260
#define PREP_SMEM ((IN_F * OUT_F + 64 * PXSTR + 4 * OUT_F) * 4)   // 133120 B

__global__ __launch_bounds__(512, 1) void prep_kernel(
    const float* __restrict__ x, const float* __restrict__ W,
    const float* __restrict__ a_i, const float* __restrict__ a_j,
    const float* __restrict__ w_g, const float* __restrict__ w_b)
{
    extern __shared__ float sm[];
    float* Ws = sm;                          // [256][64]
    float* xs = Ws + IN_F * OUT_F;           // [64][PXSTR]
    float* vs = xs + 64 * PXSTR;             // 4 x [64]

    const int t = threadIdx.x;
    const uint32_t sbase = smem_u32(sm);
    const int row0 = blockIdx.x * 64;

    // stage W (64KB) and x (64KB, padded rows) via cp.async
#pragma unroll
    for (int i = 0; i < 8; i++) {
        const int c = t + i * 512;           // 0..4095
        CP_ASYNC16(sbase + c * 16, (const char*)W + c * 16);
    }
#pragma unroll
    for (int i = 0; i < 8; i++) {
        const int c = t + i * 512;           // 0..4095
        const int row = c >> 6, k4 = c & 63;
        CP_ASYNC16(sbase + (IN_F * OUT_F + row * PXSTR + k4 * 4) * 4,
                   (const char*)(x + (size_t)(row0 + row) * IN_F) + k4 * 16);
    }
    CP_COMMIT();
    if (t < OUT_F) {
        vs[t]             = a_i[t];
        vs[OUT_F + t]     = a_j[t];
        vs[2 * OUT_F + t] = w_g[t];
        vs[3 * OUT_F + t] = w_b[t];
    }
    CP_WAIT0();
    __syncthreads();

    const int fg = t & 15;         // feature group: f0..f0+3
    const int rg = t >> 4;         // 0..31 -> rows 2rg, 2rg+1
    const int f0 = fg * 4;
    const int r0 = rg * 2, r1 = r0 + 1;

    float4 acc0 = make_float4(0.f, 0.f, 0.f, 0.f);
    float4 acc1 = make_float4(0.f, 0.f, 0.f, 0.f);
    const float*  xr0 = xs + r0 * PXSTR;
    const float*  xr1 = xs + r1 * PXSTR;
    const float4* Ws4 = (const float4*)Ws;
#pragma unroll 8
    for (int k = 0; k < IN_F; k++) {
        const float4 w4 = Ws4[k * 16 + fg];
        const float x0 = xr0[k];
        const float x1 = xr1[k];
        acc0.x = fmaf(x0, w4.x, acc0.x);
        acc0.y = fmaf(x0, w4.y, acc0.y);
        acc0.z = fmaf(x0, w4.z, acc0.z);
        acc0.w = fmaf(x0, w4.w, acc0.w);
        acc1.x = fmaf(x1, w4.x, acc1.x);
        acc1.y = fmaf(x1, w4.y, acc1.y);
        acc1.z = fmaf(x1, w4.z, acc1.z);
        acc1.w = fmaf(x1, w4.w, acc1.w);
    }

#pragma unroll
    for (int rr = 0; rr < 2; rr++) {
        const float4 acc = rr ? acc1 : acc0;
        const int grow = row0 + (rr ? r1 : r0);
        *(float4*)(g_h + (size_t)grow * OUT_F + f0) =
            make_float4(to_tf32(acc.x), to_tf32(acc.y), to_tf32(acc.z), to_tf32(acc.w));

        float psi = acc.x * vs[f0]     + acc.y * vs[f0 + 1]     + acc.z * vs[f0 + 2]     + acc.w * vs[f0 + 3];
        float psj = acc.x * vs[64+f0]  + acc.y * vs[64+f0 + 1]  + acc.z * vs[64+f0 + 2]  + acc.w * vs[64+f0 + 3];
        float pg  = acc.x * vs[128+f0] + acc.y * vs[128+f0 + 1] + acc.z * vs[128+f0 + 2] + acc.w * vs[128+f0 + 3];
        float pb  = acc.x * vs[192+f0] + acc.y * vs[192+f0 + 1] + acc.z * vs[192+f0 + 2] + acc.w * vs[192+f0 + 3];
#pragma unroll
        for (int off = 8; off > 0; off >>= 1) {
            psi += __shfl_down_sync(0xffffffffu, psi, off, 16);
            psj += __shfl_down_sync(0xffffffffu, psj, off, 16);
            pg  += __shfl_down_sync(0xffffffffu, pg,  off, 16);
            pb  += __shfl_down_sync(0xffffffffu, pb,  off, 16);
        }
        if (fg == 0) {
            g_rowEFG[grow] = make_float4(__expf(psi), __expf(LEAK * psi), 0.f, 0.f);
            g_ef[grow]     = make_float2(__expf(psj), __expf(LEAK * psj));
            g_gamma[grow]  = pg + 1.0f;
            g_beta[grow]   = pb;
        }
    }
}

// ============================================================================
// Kernel 2: fused masked softmax-attention via mma.sync tf32 + FiLM.
// EXACT round-12 kernel (best measured: 116.8us).
// 128 blocks x 1024 threads, BM=64, BN=128, 3-stage cp.async pipeline.
// ============================================================================
#define BN   128
#define ASTR 132
#define HSTR 72
#define PSTR 68

#define OFF_H    0                       // 3 x 128 x 72 = 27648 floats
#define OFF_ADJ  27648                   // 3 x 64 x 132 = 25344 (ints)
#define OFF_EF   52992                   // 3 x 256 = 768
#define OFF_DENP 53760                   // 8 x 64 = 512
#define SMEM_FLOATS 54272
#define ATTN_SMEM (SMEM_FLOATS * 4)      // 217088 B
// epilogue partials [8][64][68] = 34816 floats overlay at offset 0

__global__ __launch_bounds__(1024, 1) void attn_kernel(
    const int* __restrict__ adj, float* __restrict__ out)
{
    extern __shared__ float sf[];
    const uint32_t sbase = smem_u32(sf);

    const int t    = threadIdx.x;
    const int lane = t & 31;
    const int wid  = t >> 5;
    const int g    = lane >> 2;   // mma groupID
    const int tg   = lane & 3;    // mma threadID-in-group
    const int i0   = blockIdx.x * 64;

    const int r  = t >> 4;        // staging row 0..63
    const int cc = t & 15;        // staging chunk lane 0..15

    const int kh = wid & 7;       // K-eighth
    const int mh = wid >> 3;      // M-quarter (16 rows)

    const int m0 = mh * 16 + g;   // this thread's two w rows
    const int m1 = m0 + 8;
    const float4 efg0 = g_rowEFG[i0 + m0];
    const float4 efg1 = g_rowEFG[i0 + m1];
    const float Ei0 = efg0.x, Fi0 = efg0.y;
    const float Ei1 = efg1.x, Fi1 = efg1.y;

    const char* adj_row = (const char*)(adj + (size_t)(i0 + r) * NN);

    // hoisted staging addresses (bytes)
    const uint32_t adj_dst0 = sbase + (OFF_ADJ + r * ASTR + cc * 4) * 4;
    const uint32_t ef_dst   = sbase + (OFF_EF + t * 4) * 4;   // t<64 only
    const uint32_t ADJ_BUFB = 64 * ASTR * 4;
    const uint32_t H_BUFB   = 128 * HSTR * 4;
    const uint32_t EF_BUFB  = 256 * 4;
    const int hc0 = t, hc1 = t + 1024;
    const int hk0 = hc0 >> 4, hn0 = hc0 & 15;
    const int hk1 = hc1 >> 4, hn1 = hc1 & 15;
    const uint32_t h_dst0 = sbase + (OFF_H + hk0 * HSTR + hn0 * 4) * 4;
    const uint32_t h_dst1 = sbase + (OFF_H + hk1 * HSTR + hn1 * 4) * 4;

    // ---- prologue: prefetch tiles 0 and 1 as separate commit groups ----
#pragma unroll
    for (int pt = 0; pt < 2; pt++) {
        const uint32_t nb = pt;
        const int jj = pt * BN;
        const char* asrc = adj_row + (size_t)jj * 4;
        CP_ASYNC16(adj_dst0 + nb * ADJ_BUFB,           asrc + cc * 16);
        CP_ASYNC16(adj_dst0 + nb * ADJ_BUFB + 16 * 16, asrc + (cc + 16) * 16);
        const char* hsrc = (const char*)(g_h + (size_t)jj * OUT_F);
        CP_ASYNC16(h_dst0 + nb * H_BUFB, hsrc + hc0 * 16);
        CP_ASYNC16(h_dst1 + nb * H_BUFB, hsrc + hc1 * 16);
        if (t < 64) CP_ASYNC16(ef_dst + nb * EF_BUFB,
                               (const char*)(g_ef + jj) + t * 16);
        CP_COMMIT();
    }

    float acc[8][4];
#pragma unroll
    for (int b = 0; b < 8; b++)
#pragma unroll
        for (int c = 0; c < 4; c++) acc[b][c] = 0.0f;
    float dsum0 = 0.0f, dsum1 = 0.0f;

    uint32_t bc = 0, bn = 1, bn2 = 2;     // rotating buffer indices

    for (int tile = 0; tile < NN / BN; tile++) {
        CP_WAIT1();        // tile's group complete; tile+1 may be in flight
        __syncthreads();

        // ---- prefetch tile+2 into bn2 (or empty commit to keep counts) ----
        if (tile + 2 < NN / BN) {
            const int j2 = (tile + 2) * BN;
            const char* asrc = adj_row + (size_t)j2 * 4;
            CP_ASYNC16(adj_dst0 + bn2 * ADJ_BUFB,           asrc + cc * 16);
            CP_ASYNC16(adj_dst0 + bn2 * ADJ_BUFB + 16 * 16, asrc + (cc + 16) * 16);
            const char* hsrc = (const char*)(g_h + (size_t)j2 * OUT_F);
            CP_ASYNC16(h_dst0 + bn2 * H_BUFB, hsrc + hc0 * 16);
            CP_ASYNC16(h_dst1 + bn2 * H_BUFB, hsrc + hc1 * 16);
            if (t < 64) CP_ASYNC16(ef_dst + bn2 * EF_BUFB,
                                   (const char*)(g_ef + j2) + t * 16);
        }
        CP_COMMIT();       // empty group when no prefetch: keeps wait_group 1 exact

        // ---- fused gen + mma (per-warp; no further barriers this tile) ----
        const int*      adjS = (const int*)(sf + OFF_ADJ) + bc * (64 * ASTR);
        const float2*   efS  = (const float2*)(sf + OFF_EF) + bc * 128;
        const uint32_t* hsu  = (const uint32_t*)(sf + OFF_H) + bc * (128 * HSTR);

#pragma unroll
        for (int kc = 0; kc < 2; kc++) {
            const int k0 = kh * 16 + kc * 8;
            const int kA = k0 + tg;
            const int kB = kA + 4;
            const float2 efA = efS[kA];
            const float2 efB = efS[kB];
            const int a00 = adjS[m0 * ASTR + kA];
            const int a10 = adjS[m1 * ASTR + kA];
            const int a01 = adjS[m0 * ASTR + kB];
            const int a11 = adjS[m1 * ASTR + kB];

            float w00, w10, w01, w11;
            { const float p = Ei0 * efA.x; const float q = Fi0 * efA.y;
              w00 = (p > 1.0f) ? p : q; w00 = a00 ? w00 : 0.0f; }
            { const float p = Ei1 * efA.x; const float q = Fi1 * efA.y;
              w10 = (p > 1.0f) ? p : q; w10 = a10 ? w10 : 0.0f; }
            { const float p = Ei0 * efB.x; const float q = Fi0 * efB.y;
              w01 = (p > 1.0f) ? p : q; w01 = a01 ? w01 : 0.0f; }
            { const float p = Ei1 * efB.x; const float q = Fi1 * efB.y;
              w11 = (p > 1.0f) ? p : q; w11 = a11 ? w11 : 0.0f; }

            dsum0 += w00 + w01;
            dsum1 += w10 + w11;

            const uint32_t ka0 = __float_as_uint(to_tf32(w00));
            const uint32_t ka1 = __float_as_uint(to_tf32(w10));
            const uint32_t ka2 = __float_as_uint(to_tf32(w01));
            const uint32_t ka3 = __float_as_uint(to_tf32(w11));

#pragma unroll
            for (int nt = 0; nt < 8; nt++) {
                const uint32_t b0 = hsu[kA * HSTR + nt * 8 + g];
                const uint32_t b1 = hsu[kB * HSTR + nt * 8 + g];
                float* c = acc[nt];
                mma_tf32(c[0], c[1], c[2], c[3], ka0, ka1, ka2, ka3, b0, b1);
            }
        }

        // rotate buffers
        const uint32_t tmp = bc; bc = bn; bn = bn2; bn2 = tmp;
    }

    __syncthreads();   // all warps done with smem tiles

    // ---- denominators: reduce over tg lanes (groups of 4), stage per kh ----
    dsum0 += __shfl_down_sync(0xffffffffu, dsum0, 2, 4);
    dsum0 += __shfl_down_sync(0xffffffffu, dsum0, 1, 4);
    dsum1 += __shfl_down_sync(0xffffffffu, dsum1, 2, 4);
    dsum1 += __shfl_down_sync(0xffffffffu, dsum1, 1, 4);
    if (tg == 0) {
        sf[OFF_DENP + kh * 64 + m0] = dsum0;
        sf[OFF_DENP + kh * 64 + m1] = dsum1;
    }

    // ---- stage K-split output partials (overlay on tile smem) ----
    {
        float* part = sf + kh * (64 * PSTR);
#pragma unroll
        for (int nt = 0; nt < 8; nt++) {
            const float* c = acc[nt];
            const int n = nt * 8 + tg * 2;
            *(float2*)&part[m0 * PSTR + n] = make_float2(c[0], c[1]);
            *(float2*)&part[m1 * PSTR + n] = make_float2(c[2], c[3]);
        }
    }
    __syncthreads();

    // ---- reduce 8 partials + FiLM + store (4 outputs/thread) ----
    {
        const int m  = t >> 4;
        const int n0 = (t & 15) * 4;
        float den = 0.f;
#pragma unroll
        for (int w = 0; w < 8; w++) den += sf[OFF_DENP + w * 64 + m];
        const float inv = 1.0f / den;
        const float gm  = g_gamma[i0 + m];
        const float bt  = g_beta[i0 + m];
        float sx = 0.f, sy = 0.f, sz = 0.f, sw = 0.f;
#pragma unroll
        for (int w = 0; w < 8; w++) {
            const float4 p = *(const float4*)&sf[w * (64 * PSTR) + m * PSTR + n0];
            sx += p.x; sy += p.y; sz += p.z; sw += p.w;
        }
        *(float4*)(out + (size_t)(i0 + m) * OUT_F + n0) =
            make_float4(fmaf(gm, sx * inv, bt), fmaf(gm, sy * inv, bt),
                        fmaf(gm, sz * inv, bt), fmaf(gm, sw * inv, bt));
    }
}

// ============================================================================
extern "C" void kernel_launch(void* const* d_in, const int* in_sizes, int n_in,
                              void* d_out, int out_size)
{
    const float* x   = (const float*)d_in[0];
    const int*   adj = (const int*)d_in[1];
    const float* W   = (const float*)d_in[2];
    const float* a_i = (const float*)d_in[3];
    const float* a_j = (const float*)d_in[4];
    const float* w_g = (const float*)d_in[5];
    const float* w_b = (const float*)d_in[6];
    float* out = (float*)d_out;

    cudaFuncSetAttribute(prep_kernel, cudaFuncAttributeMaxDynamicSharedMemorySize, PREP_SMEM);
    cudaFuncSetAttribute(attn_kernel, cudaFuncAttributeMaxDynamicSharedMemorySize, ATTN_SMEM);

    prep_kernel<<<NN / 64, 512, PREP_SMEM>>>(x, W, a_i, a_j, w_g, w_b);
    attn_kernel<<<NN / 64, 1024, ATTN_SMEM>>>(adj, out);
}